// round 5
// baseline (speedup 1.0000x reference)
#include <cuda_runtime.h>
#include <math.h>

#define BATCH 131072
#define SN 32
#define H1 10
#define H2 6
#define NBLK 1024
#define ROWS_PER_BLK (BATCH / NBLK)   // 128
#define TY 8
#define NPARAM 103                     // w1(10) b1(10) -2*w1^2(10) W2(60) b2(6) w3(6) b3(1)

typedef unsigned long long u64;

// ---- static scratch (no allocations allowed) ----
__device__ float  g_partial[96 * NBLK];   // [stat*32+subnet][block]
__device__ float  g_mean[SN];
__device__ float  g_rstd[SN];

// ---- packed f32x2 helpers (FFMA2 etc., sm_100+) ----
__device__ __forceinline__ u64 f2pack(float a, float b) {
    u64 r; asm("mov.b64 %0,{%1,%2};" : "=l"(r) : "f"(a), "f"(b)); return r;
}
#define F2UNPACK(v, a, b) asm("mov.b64 {%0,%1},%2;" : "=f"(a), "=f"(b) : "l"(v))
__device__ __forceinline__ u64 fma2(u64 a, u64 b, u64 c) {
    u64 d; asm("fma.rn.f32x2 %0,%1,%2,%3;" : "=l"(d) : "l"(a), "l"(b), "l"(c)); return d;
}
__device__ __forceinline__ u64 mul2(u64 a, u64 b) {
    u64 d; asm("mul.rn.f32x2 %0,%1,%2;" : "=l"(d) : "l"(a), "l"(b)); return d;
}
__device__ __forceinline__ u64 add2(u64 a, u64 b) {
    u64 d; asm("add.rn.f32x2 %0,%1,%2;" : "=l"(d) : "l"(a), "l"(b)); return d;
}

#define ONE2  0x3F8000003F800000ULL
#define MONE2 0xBF800000BF800000ULL
#define MTWO2 0xC0000000C0000000ULL
#define C2LOG2E2 0x4038AA3B4038AA3BULL   // 2*log2(e) = 2.885390043258667f duplicated

// packed tanh via (e^{2x}-1)/(e^{2x}+1); MUFU ex2 + rcp are scalar
__device__ __forceinline__ u64 tanh2(u64 z) {
    u64 zz = mul2(z, C2LOG2E2);
    float za, zb; F2UNPACK(zz, za, zb);
    za = fminf(za, 126.0f); zb = fminf(zb, 126.0f);
    float ea, eb;
    asm("ex2.approx.f32 %0, %1;" : "=f"(ea) : "f"(za));
    asm("ex2.approx.f32 %0, %1;" : "=f"(eb) : "f"(zb));
    float ra, rb;
    asm("rcp.approx.f32 %0, %1;" : "=f"(ra) : "f"(ea + 1.0f));
    asm("rcp.approx.f32 %0, %1;" : "=f"(rb) : "f"(eb + 1.0f));
    u64 num = add2(f2pack(ea, eb), MONE2);     // e - 1
    return mul2(num, f2pack(ra, rb));
}

__global__ void __launch_bounds__(256, 2) k_forward(
    const float* __restrict__ x,
    const float* __restrict__ W1, const float* __restrict__ b1,
    const float* __restrict__ W2, const float* __restrict__ b2,
    const float* __restrict__ W3, const float* __restrict__ b3,
    float* __restrict__ out)
{
    __shared__ u64   sp2[NPARAM * 32];   // duplicated params, [param][subnet]
    __shared__ float red[3][TY][32];

    const int tx = threadIdx.x;          // subnet
    const int ty = threadIdx.y;
    const int tid = ty * 32 + tx;

    for (int p = tid; p < NPARAM * 32; p += 256) {
        int param = p >> 5, s = p & 31;
        float v;
        if      (param < 10)  v = W1[s * 10 + param];
        else if (param < 20)  v = b1[s * 10 + (param - 10)];
        else if (param < 30)  { float w = W1[s * 10 + (param - 20)]; v = -2.0f * w * w; }
        else if (param < 90)  v = W2[s * 60 + (param - 30)];          // i*6+k
        else if (param < 96)  v = b2[s * 6 + (param - 90)];
        else if (param < 102) v = W3[s * 6 + (param - 96)];
        else                  v = b3[s];
        sp2[p] = f2pack(v, v);
    }
    __syncthreads();

    const u64* spx = sp2 + tx;           // per-lane param base (stride 32)
    u64 acc_o = 0, acc_o2 = 0, acc_g = 0;
    const int row0 = blockIdx.x * ROWS_PER_BLK;

    #pragma unroll 1
    for (int it = 0; it < ROWS_PER_BLK / (TY * 2); ++it) {
        const int row = row0 + (it * TY + ty) * 2;
        const float xa = x[(size_t)row * SN + tx];
        const float xb = x[(size_t)(row + 1) * SN + tx];
        const u64 x2 = f2pack(xa, xb);

        u64 t1[H1], d1[H1], c1[H1];
        #pragma unroll
        for (int i = 0; i < H1; ++i) {
            const u64 w  = spx[(0  + i) * 32];
            const u64 bb = spx[(10 + i) * 32];
            const u64 ws = spx[(20 + i) * 32];        // -2*w^2
            const u64 t  = tanh2(fma2(w, x2, bb));
            const u64 tn = mul2(t, MONE2);
            const u64 s  = fma2(tn, t, ONE2);         // 1 - t^2
            t1[i] = t;
            d1[i] = mul2(s, w);
            c1[i] = mul2(mul2(t, s), ws);
        }

        u64 o = spx[102 * 32];
        u64 g = 0;
        #pragma unroll
        for (int k = 0; k < H2; ++k) {
            u64 z2 = spx[(90 + k) * 32];
            u64 u = 0, v = 0;
            #pragma unroll
            for (int i = 0; i < H1; ++i) {
                const u64 w = spx[(30 + i * 6 + k) * 32];
                z2 = fma2(w, t1[i], z2);
                u  = fma2(w, d1[i], u);
                v  = fma2(w, c1[i], v);
            }
            const u64 t2  = tanh2(z2);
            const u64 t2n = mul2(t2, MONE2);
            const u64 s2  = fma2(t2n, t2, ONE2);      // 1 - t2^2
            const u64 uu  = mul2(u, u);
            const u64 m2t = mul2(t2, MTWO2);          // -2*t2
            const u64 d2  = mul2(s2, fma2(m2t, uu, v));
            const u64 w3  = spx[(96 + k) * 32];
            o = fma2(w3, t2, o);
            g = fma2(w3, d2, g);
        }

        float oa, ob; F2UNPACK(o, oa, ob);
        out[(size_t)row * SN + tx]       = oa;
        out[(size_t)(row + 1) * SN + tx] = ob;
        acc_o  = add2(acc_o, o);
        acc_o2 = fma2(o, o, acc_o2);
        acc_g  = fma2(g, g, acc_g);
    }

    {
        float a, b;
        F2UNPACK(acc_o,  a, b);  red[0][ty][tx] = a + b;
        F2UNPACK(acc_o2, a, b);  red[1][ty][tx] = a + b;
        F2UNPACK(acc_g,  a, b);  red[2][ty][tx] = a + b;
    }
    __syncthreads();
    if (ty < 3) {
        float s = 0.0f;
        #pragma unroll
        for (int j = 0; j < TY; ++j) s += red[ty][j][tx];
        g_partial[(ty * 32 + tx) * NBLK + blockIdx.x] = s;
    }
}

// fused final reduction + batch-norm stats + smooth loss (one block)
__global__ void k_reduce_stats(float* __restrict__ out, int write_loss)
{
    __shared__ double sred[96][8];
    __shared__ double ssum[96];

    const int tid = threadIdx.x;         // 768 threads
    const int pair = tid >> 3;           // 0..95 = stat*32 + subnet
    const int j    = tid & 7;

    const float4* src = (const float4*)(g_partial + pair * NBLK + j * (NBLK / 8));
    double s0 = 0.0, s1 = 0.0;
    #pragma unroll 4
    for (int i = 0; i < NBLK / 32; ++i) {           // 32 float4 per thread
        float4 v = src[i];
        s0 += (double)(v.x + v.y);
        s1 += (double)(v.z + v.w);
    }
    sred[pair][j] = s0 + s1;
    __syncthreads();

    if (tid < 96) {
        double s = 0.0;
        #pragma unroll
        for (int q = 0; q < 8; ++q) s += sred[tid][q];
        ssum[tid] = s;
    }
    __syncthreads();

    if (tid < 32) {
        const double n   = (double)BATCH;
        const double so  = ssum[0 * 32 + tid];
        const double so2 = ssum[1 * 32 + tid];
        const double sg  = ssum[2 * 32 + tid];
        const double mean = so / n;
        const double var  = so2 / n - mean * mean;
        g_mean[tid] = (float)mean;
        g_rstd[tid] = (float)(1.0 / sqrt(var + 1e-10));
        double pen = (sg / n) / sqrt(var);
        #pragma unroll
        for (int o = 16; o > 0; o >>= 1)
            pen += __shfl_down_sync(0xffffffffu, pen, o);
        if (tid == 0 && write_loss)
            out[(size_t)BATCH * SN] = (float)(0.001 * pen);
    }
}

__global__ void __launch_bounds__(256) k_norm(float* __restrict__ out)
{
    __shared__ float sm[32], sr[32];
    if (threadIdx.x < 32) {
        sm[threadIdx.x] = g_mean[threadIdx.x];
        sr[threadIdx.x] = g_rstd[threadIdx.x];
    }
    __syncthreads();
    const size_t stride = (size_t)2048 * 256 * 4;
    const size_t idx0 = ((size_t)blockIdx.x * blockDim.x + threadIdx.x) * 4;
    const size_t idx1 = idx0 + stride;

    float4 v0 = *reinterpret_cast<float4*>(out + idx0);   // issue both loads (MLP=2)
    float4 v1 = *reinterpret_cast<float4*>(out + idx1);
    const int s0 = (int)(idx0 & 31);
    const int s1 = (int)(idx1 & 31);

    v0.x = (v0.x - sm[s0 + 0]) * sr[s0 + 0];
    v0.y = (v0.y - sm[s0 + 1]) * sr[s0 + 1];
    v0.z = (v0.z - sm[s0 + 2]) * sr[s0 + 2];
    v0.w = (v0.w - sm[s0 + 3]) * sr[s0 + 3];
    v1.x = (v1.x - sm[s1 + 0]) * sr[s1 + 0];
    v1.y = (v1.y - sm[s1 + 1]) * sr[s1 + 1];
    v1.z = (v1.z - sm[s1 + 2]) * sr[s1 + 2];
    v1.w = (v1.w - sm[s1 + 3]) * sr[s1 + 3];

    *reinterpret_cast<float4*>(out + idx0) = v0;
    *reinterpret_cast<float4*>(out + idx1) = v1;
}

extern "C" void kernel_launch(void* const* d_in, const int* in_sizes, int n_in,
                              void* d_out, int out_size)
{
    const float* x  = (const float*)d_in[0];
    const float* W1 = (const float*)d_in[1];
    const float* b1 = (const float*)d_in[2];
    const float* W2 = (const float*)d_in[3];
    const float* b2 = (const float*)d_in[4];
    const float* W3 = (const float*)d_in[5];
    const float* b3 = (const float*)d_in[6];
    float* out = (float*)d_out;

    dim3 blk(32, TY);
    k_forward<<<NBLK, blk>>>(x, W1, b1, W2, b2, W3, b3, out);
    const int write_loss = (out_size > BATCH * SN) ? 1 : 0;
    k_reduce_stats<<<1, 768>>>(out, write_loss);
    k_norm<<<2048, 256>>>(out);
}

// round 7
// speedup vs baseline: 1.2672x; 1.2672x over previous
#include <cuda_runtime.h>
#include <math.h>

#define BATCH 131072
#define SN 32
#define H1 10
#define H2 6
#define NBLK 1024
#define ROWS_PER_BLK (BATCH / NBLK)   // 128
#define TY 8
#define NPARAM 103                     // w1(10) b1(10) -2*w1^2(10) W2(60) b2(6) w3(6) b3(1)

typedef unsigned long long u64;

// ---- static scratch (no allocations allowed) ----
__device__ float  g_partial[96 * NBLK];   // [stat*32+subnet][block]
__device__ float  g_mean[SN];
__device__ float  g_rstd[SN];

// ---- packed f32x2 helpers (FFMA2 etc., sm_100+) ----
__device__ __forceinline__ u64 f2pack(float a, float b) {
    u64 r; asm("mov.b64 %0,{%1,%2};" : "=l"(r) : "f"(a), "f"(b)); return r;
}
__device__ __forceinline__ u64 f2dup(float a) {
    u64 r; asm("mov.b64 %0,{%1,%1};" : "=l"(r) : "f"(a)); return r;
}
#define F2UNPACK(v, a, b) asm("mov.b64 {%0,%1},%2;" : "=f"(a), "=f"(b) : "l"(v))
__device__ __forceinline__ u64 fma2(u64 a, u64 b, u64 c) {
    u64 d; asm("fma.rn.f32x2 %0,%1,%2,%3;" : "=l"(d) : "l"(a), "l"(b), "l"(c)); return d;
}
__device__ __forceinline__ u64 mul2(u64 a, u64 b) {
    u64 d; asm("mul.rn.f32x2 %0,%1,%2;" : "=l"(d) : "l"(a), "l"(b)); return d;
}
__device__ __forceinline__ u64 add2(u64 a, u64 b) {
    u64 d; asm("add.rn.f32x2 %0,%1,%2;" : "=l"(d) : "l"(a), "l"(b)); return d;
}

#define ONE2  0x3F8000003F800000ULL
#define MONE2 0xBF800000BF800000ULL
#define MTWO2 0xC0000000C0000000ULL
#define C2LOG2E2 0x4038AA3B4038AA3BULL   // 2*log2(e) duplicated

// packed tanh via (e^{2x}-1)/(e^{2x}+1); one shared rcp for both lanes:
// r = rcp((ea+1)(eb+1));  1/(ea+1) = r*(eb+1);  1/(eb+1) = r*(ea+1)
// inputs bounded (|z| < 60) so no overflow clamp needed.
__device__ __forceinline__ u64 tanh2(u64 z) {
    float za, zb;
    F2UNPACK(mul2(z, C2LOG2E2), za, zb);
    float ea, eb;
    asm("ex2.approx.f32 %0, %1;" : "=f"(ea) : "f"(za));
    asm("ex2.approx.f32 %0, %1;" : "=f"(eb) : "f"(zb));
    const float pa = ea + 1.0f, pb = eb + 1.0f;
    float r;
    asm("rcp.approx.f32 %0, %1;" : "=f"(r) : "f"(pa * pb));
    return mul2(add2(f2pack(ea, eb), MONE2), f2pack(r * pb, r * pa));
}

__global__ void __launch_bounds__(256, 3) k_forward(
    const float* __restrict__ x,
    const float* __restrict__ W1, const float* __restrict__ b1,
    const float* __restrict__ W2, const float* __restrict__ b2,
    const float* __restrict__ W3, const float* __restrict__ b3,
    float* __restrict__ out)
{
    __shared__ float sp[NPARAM * 32];    // scalar params, [param][subnet] -> conflict-free
    __shared__ float red[3][TY][32];

    const int tx = threadIdx.x;          // subnet
    const int ty = threadIdx.y;
    const int tid = ty * 32 + tx;

    for (int p = tid; p < NPARAM * 32; p += 256) {
        int param = p >> 5, s = p & 31;
        float v;
        if      (param < 10)  v = W1[s * 10 + param];
        else if (param < 20)  v = b1[s * 10 + (param - 10)];
        else if (param < 30)  { float w = W1[s * 10 + (param - 20)]; v = -2.0f * w * w; }
        else if (param < 90)  v = W2[s * 60 + (param - 30)];          // i*6+k
        else if (param < 96)  v = b2[s * 6 + (param - 90)];
        else if (param < 102) v = W3[s * 6 + (param - 96)];
        else                  v = b3[s];
        sp[p] = v;
    }
    __syncthreads();

    const float* spx = sp + tx;          // per-lane param base (stride 32)
    u64 acc_o = 0, acc_o2 = 0, acc_g = 0;
    const int row0 = blockIdx.x * ROWS_PER_BLK;

    #pragma unroll 1
    for (int it = 0; it < ROWS_PER_BLK / (TY * 2); ++it) {
        const int row = row0 + (it * TY + ty) * 2;
        const float xa = x[(size_t)row * SN + tx];
        const float xb = x[(size_t)(row + 1) * SN + tx];
        const u64 x2 = f2pack(xa, xb);

        // accumulators for layer-2 pre-activations and their 1st/2nd-deriv parts
        u64 z2[H2], u[H2], v[H2];
        #pragma unroll
        for (int k = 0; k < H2; ++k) {
            z2[k] = f2dup(spx[(90 + k) * 32]);
            u[k] = 0;  v[k] = 0;
        }

        #pragma unroll
        for (int i = 0; i < H1; ++i) {
            const float w  = spx[(0  + i) * 32];
            const float bb = spx[(10 + i) * 32];
            const float ws = spx[(20 + i) * 32];        // -2*w^2
            const u64 t  = tanh2(fma2(f2dup(w), x2, f2dup(bb)));
            const u64 tn = mul2(t, MONE2);
            const u64 s  = fma2(tn, t, ONE2);           // 1 - t^2
            const u64 d  = mul2(s, f2dup(w));           // (1-t^2) w
            const u64 c  = mul2(mul2(t, s), f2dup(ws)); // -2 t (1-t^2) w^2
            #pragma unroll
            for (int k = 0; k < H2; ++k) {
                const u64 w2 = f2dup(spx[(30 + i * 6 + k) * 32]);
                z2[k] = fma2(w2, t, z2[k]);
                u[k]  = fma2(w2, d, u[k]);
                v[k]  = fma2(w2, c, v[k]);
            }
        }

        u64 o = f2dup(spx[102 * 32]);
        u64 g = 0;
        #pragma unroll
        for (int k = 0; k < H2; ++k) {
            const u64 t2  = tanh2(z2[k]);
            const u64 t2n = mul2(t2, MONE2);
            const u64 s2  = fma2(t2n, t2, ONE2);        // 1 - t2^2
            const u64 uu  = mul2(u[k], u[k]);
            const u64 m2t = mul2(t2, MTWO2);            // -2*t2
            const u64 d2  = mul2(s2, fma2(m2t, uu, v[k]));
            const u64 w3  = f2dup(spx[(96 + k) * 32]);
            o = fma2(w3, t2, o);
            g = fma2(w3, d2, g);
        }

        float oa, ob; F2UNPACK(o, oa, ob);
        out[(size_t)row * SN + tx]       = oa;
        out[(size_t)(row + 1) * SN + tx] = ob;
        acc_o  = add2(acc_o, o);
        acc_o2 = fma2(o, o, acc_o2);
        acc_g  = fma2(g, g, acc_g);
    }

    {
        float a, b;
        F2UNPACK(acc_o,  a, b);  red[0][ty][tx] = a + b;
        F2UNPACK(acc_o2, a, b);  red[1][ty][tx] = a + b;
        F2UNPACK(acc_g,  a, b);  red[2][ty][tx] = a + b;
    }
    __syncthreads();
    if (ty < 3) {
        float s = 0.0f;
        #pragma unroll
        for (int j = 0; j < TY; ++j) s += red[ty][j][tx];
        g_partial[(ty * 32 + tx) * NBLK + blockIdx.x] = s;
    }
}

// fused final reduction + batch-norm stats + smooth loss (one block)
__global__ void k_reduce_stats(float* __restrict__ out, int write_loss)
{
    __shared__ double sred[96][8];
    __shared__ double ssum[96];

    const int tid = threadIdx.x;         // 768 threads
    const int pair = tid >> 3;           // 0..95 = stat*32 + subnet
    const int j    = tid & 7;

    const float4* src = (const float4*)(g_partial + pair * NBLK + j * (NBLK / 8));
    double s0 = 0.0, s1 = 0.0;
    #pragma unroll 4
    for (int i = 0; i < NBLK / 32; ++i) {           // 32 float4 per thread
        float4 v = src[i];
        s0 += (double)(v.x + v.y);
        s1 += (double)(v.z + v.w);
    }
    sred[pair][j] = s0 + s1;
    __syncthreads();

    if (tid < 96) {
        double s = 0.0;
        #pragma unroll
        for (int q = 0; q < 8; ++q) s += sred[tid][q];
        ssum[tid] = s;
    }
    __syncthreads();

    if (tid < 32) {
        const double n   = (double)BATCH;
        const double so  = ssum[0 * 32 + tid];
        const double so2 = ssum[1 * 32 + tid];
        const double sg  = ssum[2 * 32 + tid];
        const double mean = so / n;
        const double var  = so2 / n - mean * mean;
        g_mean[tid] = (float)mean;
        g_rstd[tid] = (float)(1.0 / sqrt(var + 1e-10));
        double pen = (sg / n) / sqrt(var);
        #pragma unroll
        for (int o = 16; o > 0; o >>= 1)
            pen += __shfl_down_sync(0xffffffffu, pen, o);
        if (tid == 0 && write_loss)
            out[(size_t)BATCH * SN] = (float)(0.001 * pen);
    }
}

__global__ void __launch_bounds__(256) k_norm(float* __restrict__ out)
{
    __shared__ float sm[32], sr[32];
    if (threadIdx.x < 32) {
        sm[threadIdx.x] = g_mean[threadIdx.x];
        sr[threadIdx.x] = g_rstd[threadIdx.x];
    }
    __syncthreads();
    const size_t stride = (size_t)2048 * 256 * 4;
    const size_t idx0 = ((size_t)blockIdx.x * blockDim.x + threadIdx.x) * 4;
    const size_t idx1 = idx0 + stride;

    float4 v0 = *reinterpret_cast<float4*>(out + idx0);   // issue both loads (MLP=2)
    float4 v1 = *reinterpret_cast<float4*>(out + idx1);
    const int s0 = (int)(idx0 & 31);
    const int s1 = (int)(idx1 & 31);

    v0.x = (v0.x - sm[s0 + 0]) * sr[s0 + 0];
    v0.y = (v0.y - sm[s0 + 1]) * sr[s0 + 1];
    v0.z = (v0.z - sm[s0 + 2]) * sr[s0 + 2];
    v0.w = (v0.w - sm[s0 + 3]) * sr[s0 + 3];
    v1.x = (v1.x - sm[s1 + 0]) * sr[s1 + 0];
    v1.y = (v1.y - sm[s1 + 1]) * sr[s1 + 1];
    v1.z = (v1.z - sm[s1 + 2]) * sr[s1 + 2];
    v1.w = (v1.w - sm[s1 + 3]) * sr[s1 + 3];

    *reinterpret_cast<float4*>(out + idx0) = v0;
    *reinterpret_cast<float4*>(out + idx1) = v1;
}

extern "C" void kernel_launch(void* const* d_in, const int* in_sizes, int n_in,
                              void* d_out, int out_size)
{
    const float* x  = (const float*)d_in[0];
    const float* W1 = (const float*)d_in[1];
    const float* b1 = (const float*)d_in[2];
    const float* W2 = (const float*)d_in[3];
    const float* b2 = (const float*)d_in[4];
    const float* W3 = (const float*)d_in[5];
    const float* b3 = (const float*)d_in[6];
    float* out = (float*)d_out;

    dim3 blk(32, TY);
    k_forward<<<NBLK, blk>>>(x, W1, b1, W2, b2, W3, b3, out);
    const int write_loss = (out_size > BATCH * SN) ? 1 : 0;
    k_reduce_stats<<<1, 768>>>(out, write_loss);
    k_norm<<<2048, 256>>>(out);
}